// round 6
// baseline (speedup 1.0000x reference)
#include <cuda_runtime.h>
#include <math.h>

#define NB 2
#define NN 4096
#define MM 512
#define KK 50
#define EPSc 1e-5

// ---------------- scratch layout (floats) ----------------
#define F_XP3   0
#define F_XGP3  (F_XP3+NB*NN*3)
#define F_X1    (F_XGP3+NB*MM*3)
#define F_X2    (F_X1+NB*NN*64)
#define F_X3    (F_X2+NB*NN*64)
#define F_X1G   (F_X3+NB*NN*64)
#define F_X2G   (F_X1G+NB*MM*64)
#define F_X3G   (F_X2G+NB*MM*64)
#define F_P     (F_X3G+NB*MM*64)
#define F_R     (F_P+NB*NN*64)
#define F_Q     (F_R+NB*NN*64)
#define F_GNRM  (F_Q+NB*MM*64)
#define F_MAXB  (F_GNRM+NB*MM)
#define F_Y7    (F_MAXB+NB*NN*64)
#define F_Y8    (F_Y7+NB*NN*128)
#define F_W6T   (F_Y8+NB*NN*64)
#define F_W7BT  (F_W6T+192*512)
#define F_W8T   (F_W7BT+192*128)
#define F_W9T   (F_W8T+128*64)
#define F_W2T   (F_W9T+64*128)
#define F_W4T   (F_W2T+64*64)
#define F_C7    (F_W4T+64*64)
#define F_SC0   (F_C7+NB*128)
#define F_BI0   (F_SC0+512)
#define F_SC1   (F_BI0+512)
#define F_BI1   (F_SC1+512)
#define F_TOT   (F_BI1+512)

__device__ float g_f[F_TOT];
__device__ double g_d[2048];
__device__ unsigned long long g_near[NB*NN];
__device__ int g_nbr[NB*MM*KK];
__device__ unsigned g_max6[NB*512];

__device__ __forceinline__ unsigned long long packkey(float d, int m){
    unsigned u = __float_as_uint(d);
    u = (u & 0x80000000u) ? ~u : (u | 0x80000000u);
    return (((unsigned long long)u) << 32) | (unsigned)m;
}
__device__ __forceinline__ unsigned f2ord(float x){
    unsigned u = __float_as_uint(x);
    return (u & 0x80000000u) ? ~u : (u | 0x80000000u);
}
__device__ __forceinline__ float ord2f(unsigned u){
    return (u & 0x80000000u) ? __uint_as_float(u ^ 0x80000000u) : __uint_as_float(~u);
}

// ---------------- prep: channel-major -> point-major ----------------
__global__ void k_prep(const float* __restrict__ x, const float* __restrict__ xg,
                       float* __restrict__ xp, float* __restrict__ xgp){
    int i = blockIdx.x*blockDim.x + threadIdx.x;
    if (i < NB*NN*3){
        int b = i/(NN*3); int rem = i - b*NN*3; int n = rem/3; int c = rem - n*3;
        xp[i] = x[(b*3 + c)*NN + n];
    }
    if (i < NB*MM*3){
        int b = i/(MM*3); int rem = i - b*MM*3; int m = rem/3; int c = rem - m*3;
        xgp[i] = xg[(b*3 + c)*MM + m];
    }
}

// ---------------- weight transposes ----------------
__global__ void k_wt(const float* __restrict__ W2, const float* __restrict__ W4,
                     const float* __restrict__ W6, const float* __restrict__ W7,
                     const float* __restrict__ W8, const float* __restrict__ W9,
                     float* __restrict__ W2T, float* __restrict__ W4T,
                     float* __restrict__ W6T, float* __restrict__ W7BT,
                     float* __restrict__ W8T, float* __restrict__ W9T){
    int i = blockIdx.x*blockDim.x + threadIdx.x;
    if (i < 512*192){ int o=i/192, c=i-o*192; W6T[c*512+o] = W6[i]; }
    if (i < 128*192){ int o=i/192, c=i-o*192; W7BT[c*128+o] = W7[o*704+512+c]; }
    if (i < 64*128){ int o=i>>7, c=i&127; W8T[c*64+o] = W8[i]; }
    if (i < 128*64){ int o=i>>6, c=i&63; W9T[c*128+o] = W9[i]; }
    if (i < 64*64){ int o=i>>6, c=i&63; W2T[c*64+o] = W2[i]; W4T[c*64+o] = W4[i]; }
}

// ---------------- |g|^2 per grid point ----------------
template<int C>
__global__ void k_gn(const float* __restrict__ G, float* __restrict__ gn){
    int i = blockIdx.x*blockDim.x + threadIdx.x;
    if (i >= NB*MM) return;
    const float* Gp = G + (size_t)i*C;
    float s = 0.f;
    #pragma unroll
    for (int c = 0; c < C; c++) s = fmaf(Gp[c], Gp[c], s);
    gn[i] = s;
}

__global__ void k_initnear(){
    int i = blockIdx.x*blockDim.x + threadIdx.x;
    if (i < NB*NN) g_near[i] = ~0ULL;
}
__global__ void k_zero(double* __restrict__ s, double* __restrict__ q){
    int i = threadIdx.x; s[i] = 0.0; q[i] = 0.0;
}
__global__ void k_zero6(){
    int i = threadIdx.x; if (i < NB*512) g_max6[i] = 0u;
}

// ---------------- nearest grid point per point ----------------
template<int C>
__global__ void k_nearest(const float* __restrict__ X, const float* __restrict__ G,
                          const float* __restrict__ gn){
    const int TM = 64;
    int b  = blockIdx.z;
    int m0 = blockIdx.y * TM;
    int n  = blockIdx.x * blockDim.x + threadIdx.x;
    __shared__ float sg[TM*C];
    __shared__ float sgn[TM];
    const float* Gb = G + ((size_t)b*MM + m0)*C;
    for (int i = threadIdx.x; i < TM*C; i += blockDim.x) sg[i] = Gb[i];
    for (int i = threadIdx.x; i < TM;   i += blockDim.x) sgn[i] = gn[b*MM + m0 + i];
    __syncthreads();
    float xr[C];
    const float* Xp = X + ((size_t)b*NN + n)*C;
    #pragma unroll
    for (int c = 0; c < C; c++) xr[c] = Xp[c];
    float best = INFINITY; int bi = 0;
    for (int j = 0; j < TM; j++){
        float dot = 0.f;
        #pragma unroll
        for (int c = 0; c < C; c++) dot = fmaf(xr[c], sg[j*C + c], dot);
        float d = sgn[j] - 2.f*dot;
        if (d < best){ best = d; bi = m0 + j; }
    }
    atomicMin(&g_near[(size_t)b*NN + n], packkey(best, bi));
}

// ---------------- 50 nearest grid neighbors of each grid point ----------------
template<int C>
__global__ void k_nbr(const float* __restrict__ G, const float* __restrict__ gn){
    int b = blockIdx.x >> 9, m = blockIdx.x & 511;
    __shared__ float sd[MM];
    __shared__ float sgm[C];
    __shared__ float wv[4]; __shared__ int wi[4];
    int tid = threadIdx.x;
    const float* Gb = G + (size_t)b*MM*C;
    for (int c = tid; c < C; c += 128) sgm[c] = Gb[(size_t)m*C + c];
    __syncthreads();
    float gm = gn[b*MM + m];
    for (int j = tid; j < MM; j += 128){
        float dot = 0.f;
        #pragma unroll 8
        for (int c = 0; c < C; c++) dot = fmaf(sgm[c], Gb[(size_t)j*C + c], dot);
        sd[j] = (j == m) ? -INFINITY : (gm + gn[b*MM + j] - 2.f*dot);
    }
    __syncthreads();
    for (int k = 0; k < KK; k++){
        float bv = INFINITY; int bj = 0x7fffffff;
        #pragma unroll
        for (int t = 0; t < 4; t++){
            int j = tid + t*128; float v = sd[j];
            if (v < bv || (v == bv && j < bj)){ bv = v; bj = j; }
        }
        for (int off = 16; off; off >>= 1){
            float ov = __shfl_down_sync(0xffffffffu, bv, off);
            int   oi = __shfl_down_sync(0xffffffffu, bj, off);
            if (ov < bv || (ov == bv && oi < bj)){ bv = ov; bj = oi; }
        }
        if ((tid & 31) == 0){ wv[tid>>5] = bv; wi[tid>>5] = bj; }
        __syncthreads();
        if (tid == 0){
            for (int w = 1; w < 4; w++)
                if (wv[w] < bv || (wv[w] == bv && wi[w] < bj)){ bv = wv[w]; bj = wi[w]; }
            g_nbr[(size_t)blockIdx.x*KK + k] = bj;
            sd[bj] = INFINITY;
        }
        __syncthreads();
    }
}

// ---------------- P,R (points) / Q (grid) projections ----------------
template<int C>
__global__ void k_pqr(const float* __restrict__ X, const float* __restrict__ W,
                      float* __restrict__ P, float* __restrict__ R, int npts){
    int i = blockIdx.x*blockDim.x + threadIdx.x;
    if (i >= npts*64) return;
    int o = i & 63; int pn = i >> 6;
    const float* Xp = X + (size_t)pn*C;
    const float* Wo = W + (size_t)o*2*C;
    float p = 0.f, r = 0.f;
    #pragma unroll
    for (int c = 0; c < C; c++){
        float xv = Xp[c]; float wl = Wo[c]; float wh = Wo[C + c];
        p = fmaf(wh - wl, xv, p);
        r = fmaf(wl, xv, r);
    }
    P[i] = p; R[i] = r;
}

template<int C>
__global__ void k_q(const float* __restrict__ G, const float* __restrict__ W,
                    float* __restrict__ Q, int npts){
    int i = blockIdx.x*blockDim.x + threadIdx.x;
    if (i >= npts*64) return;
    int o = i & 63; int pm = i >> 6;
    const float* Gp = G + (size_t)pm*C;
    const float* Wo = W + (size_t)o*2*C;
    float q = 0.f;
    #pragma unroll
    for (int c = 0; c < C; c++) q = fmaf(Wo[c], Gp[c], q);
    Q[i] = q;
}

// ---------------- stats (and optional max) of y_a = P + (k? Q[nbr] : R) ----------------
__global__ void k_stats_a(const float* __restrict__ P, const float* __restrict__ R,
                          const float* __restrict__ Q,
                          double* __restrict__ gsum, double* __restrict__ gsq,
                          float* __restrict__ gmax, int withmax){
    __shared__ int snbr[2][KK];
    int tid = threadIdx.x; int slot = tid >> 6; int o = tid & 63;
    double dsum = 0.0, dsq = 0.0;
    for (int it = 0; it < 8; ++it){
        int pn = blockIdx.x*16 + it*2 + slot;
        int b = pn >> 12;
        int near = (int)(g_near[pn] & 0xFFFFFFFFu);
        const int* row = g_nbr + ((size_t)(b*MM + near))*KK;
        if (o < KK) snbr[slot][o] = row[o];
        __syncthreads();
        float p = P[(size_t)pn*64 + o], r = R[(size_t)pn*64 + o];
        float v = p + r;
        float fs = v, fq = v*v, mx = v;
        for (int k = 1; k < KK; k++){
            int m = snbr[slot][k];
            v = p + Q[((size_t)(b*MM + m))*64 + o];
            fs += v; fq += v*v; mx = fmaxf(mx, v);
        }
        if (withmax) gmax[(size_t)pn*64 + o] = mx;
        dsum += fs; dsq += fq;
        __syncthreads();
    }
    atomicAdd(&gsum[o], dsum);
    atomicAdd(&gsq[o], dsq);
}

// ---------------- BN params ----------------
__global__ void k_bnparams(const double* __restrict__ sum, const double* __restrict__ sq,
                           const float* __restrict__ gma, const float* __restrict__ bta,
                           int nch, double cnt, float* __restrict__ sc, float* __restrict__ bi){
    int o = threadIdx.x;
    if (o >= nch) return;
    double mean = sum[o]/cnt;
    double var = sq[o]/cnt - mean*mean;
    if (var < 0.0) var = 0.0;
    double s = (double)gma[o] / sqrt(var + (double)EPSc);
    sc[o] = (float)s;
    bi[o] = (float)((double)bta[o] - mean*s);
}

// ---------------- fused second edge-conv: h=lrelu(bnA(y_a)); y_b=Wb*h; stats+max ----------------
__global__ void __launch_bounds__(128)
k_convb(const float* __restrict__ P, const float* __restrict__ R, const float* __restrict__ Q,
        const float* __restrict__ WT, const float* __restrict__ scA, const float* __restrict__ biA,
        float* __restrict__ gmax, double* __restrict__ gsum, double* __restrict__ gsq){
    __shared__ float4 sh4[2][2][16];
    __shared__ int snbr[2][KK];
    int tid = threadIdx.x, slot = tid >> 6, o = tid & 63;
    float Wrow[64];
    #pragma unroll
    for (int c = 0; c < 64; c++) Wrow[c] = WT[c*64 + o];
    float sc = scA[o], bi = biA[o];
    double dsum = 0.0, dsq = 0.0;
    for (int it = 0; it < 2; ++it){
        int pn = blockIdx.x*4 + it*2 + slot;
        int b = pn >> 12;
        int near = (int)(g_near[pn] & 0xFFFFFFFFu);
        const int* row = g_nbr + ((size_t)(b*MM + near))*KK;
        if (o < KK) snbr[slot][o] = row[o];
        __syncthreads();
        float p = P[(size_t)pn*64 + o], r = R[(size_t)pn*64 + o];
        float fs = 0.f, fq = 0.f, mx = -INFINITY;
        for (int k = 0; k < KK; k++){
            float v = p + ((k == 0) ? r : Q[((size_t)(b*MM + snbr[slot][k]))*64 + o]);
            float hv = fmaf(v, sc, bi);
            hv = (hv >= 0.f) ? hv : 0.2f*hv;
            ((float*)sh4[k & 1][slot])[o] = hv;
            __syncthreads();
            const float4* h4 = sh4[k & 1][slot];
            float y = 0.f;
            #pragma unroll
            for (int c4 = 0; c4 < 16; c4++){
                float4 h = h4[c4];
                y = fmaf(Wrow[4*c4+0], h.x, y);
                y = fmaf(Wrow[4*c4+1], h.y, y);
                y = fmaf(Wrow[4*c4+2], h.z, y);
                y = fmaf(Wrow[4*c4+3], h.w, y);
            }
            fs += y; fq += y*y; mx = fmaxf(mx, y);
        }
        gmax[(size_t)pn*64 + o] = mx;
        dsum += fs; dsq += fq;
        __syncthreads();
    }
    atomicAdd(&gsum[o], dsum);
    atomicAdd(&gsq[o], dsq);
}

// ---------------- x_s = lrelu(bn(max)); gather ----------------
__global__ void k_x(const float* __restrict__ gmax, const float* __restrict__ sc,
                    const float* __restrict__ bi, float* __restrict__ X){
    int i = blockIdx.x*blockDim.x + threadIdx.x;
    if (i >= NB*NN*64) return;
    int o = i & 63;
    float v = fmaf(gmax[i], sc[o], bi[o]);
    X[i] = (v >= 0.f) ? v : 0.2f*v;
}

__global__ void k_gather(const float* __restrict__ X, const int* __restrict__ FPS,
                         float* __restrict__ XG){
    int i = blockIdx.x*blockDim.x + threadIdx.x;
    if (i >= NB*MM*64) return;
    int o = i & 63; int pm = i >> 6; int b = pm >> 9; int m = pm & 511;
    int n = FPS[b*MM + m];
    XG[i] = X[(((size_t)b*NN) + n)*64 + o];
}

// ---------------- y6 = W6 * [x1g;x2g;x3g], fused stats + per-(b,o) max ----------------
__global__ void k_y6stats(const float* __restrict__ x1g, const float* __restrict__ x2g,
                          const float* __restrict__ x3g, const float* __restrict__ WT,
                          double* __restrict__ gsum, double* __restrict__ gsq){
    __shared__ float sF[16][192];
    int tid = threadIdx.x; int pm0 = blockIdx.x*16; int b = pm0 >> 9;
    for (int idx = tid; idx < 16*192; idx += 128){
        int p = idx/192, c = idx - p*192; int pm = pm0 + p;
        float v = (c < 64) ? x1g[(size_t)pm*64 + c]
                : (c < 128) ? x2g[(size_t)pm*64 + c - 64]
                            : x3g[(size_t)pm*64 + c - 128];
        sF[p][c] = v;
    }
    __syncthreads();
    int o = blockIdx.y*128 + tid;
    double s = 0.0, q = 0.0; float mx = -INFINITY;
    for (int p0 = 0; p0 < 16; p0 += 4){
        float a0=0.f,a1=0.f,a2=0.f,a3=0.f;
        for (int c = 0; c < 192; c++){
            float w = WT[c*512 + o];
            a0 = fmaf(w, sF[p0+0][c], a0);
            a1 = fmaf(w, sF[p0+1][c], a1);
            a2 = fmaf(w, sF[p0+2][c], a2);
            a3 = fmaf(w, sF[p0+3][c], a3);
        }
        s += (double)a0 + (double)a1 + (double)a2 + (double)a3;
        q += (double)a0*a0 + (double)a1*a1 + (double)a2*a2 + (double)a3*a3;
        mx = fmaxf(fmaxf(fmaxf(mx, a0), fmaxf(a1, a2)), a3);
    }
    atomicAdd(&gsum[o], s);
    atomicAdd(&gsq[o], q);
    atomicMax(&g_max6[b*512 + o], f2ord(mx));
}

// ---------------- c7[b,o] = W7[:, :512] . lrelu(bn6(y6max)) ----------------
__global__ void k_c7(const float* __restrict__ W7, const float* __restrict__ sc,
                     const float* __restrict__ bi, float* __restrict__ c7){
    int t = threadIdx.x; int b = t >> 7, o = t & 127;
    float acc = 0.f;
    for (int c = 0; c < 512; c++){
        float v = ord2f(g_max6[b*512 + c]);
        float h = fmaf(v, sc[c], bi[c]);
        h = (h >= 0.f) ? h : 0.2f*h;
        acc = fmaf(W7[(size_t)o*704 + c], h, acc);
    }
    c7[t] = acc;
}

// ---------------- y7 = c7 + W7[:,512:] * [x1;x2;x3], stats ----------------
__global__ void k_y7(const float* __restrict__ x1, const float* __restrict__ x2,
                     const float* __restrict__ x3, const float* __restrict__ WT,
                     const float* __restrict__ c7, float* __restrict__ y7,
                     double* __restrict__ gsum, double* __restrict__ gsq){
    __shared__ float sF[16][192];
    int tid = threadIdx.x; int pn0 = blockIdx.x*16; int b = pn0 >> 12;
    for (int idx = tid; idx < 16*192; idx += 128){
        int p = idx/192, c = idx - p*192; int pn = pn0 + p;
        float v = (c < 64) ? x1[(size_t)pn*64 + c]
                : (c < 128) ? x2[(size_t)pn*64 + c - 64]
                            : x3[(size_t)pn*64 + c - 128];
        sF[p][c] = v;
    }
    __syncthreads();
    int o = tid;
    float ci = c7[b*128 + o];
    double s = 0.0, q = 0.0;
    for (int p0 = 0; p0 < 16; p0 += 4){
        float a0=ci,a1=ci,a2=ci,a3=ci;
        for (int c = 0; c < 192; c++){
            float w = WT[c*128 + o];
            a0 = fmaf(w, sF[p0+0][c], a0);
            a1 = fmaf(w, sF[p0+1][c], a1);
            a2 = fmaf(w, sF[p0+2][c], a2);
            a3 = fmaf(w, sF[p0+3][c], a3);
        }
        y7[(size_t)(pn0+p0+0)*128 + o] = a0;
        y7[(size_t)(pn0+p0+1)*128 + o] = a1;
        y7[(size_t)(pn0+p0+2)*128 + o] = a2;
        y7[(size_t)(pn0+p0+3)*128 + o] = a3;
        s += (double)a0 + (double)a1 + (double)a2 + (double)a3;
        q += (double)a0*a0 + (double)a1*a1 + (double)a2*a2 + (double)a3*a3;
    }
    atomicAdd(&gsum[o], s);
    atomicAdd(&gsq[o], q);
}

// ---------------- y8 = W8 * lrelu(bn7(y7)), stats ----------------
__global__ void k_y8(const float* __restrict__ y7, const float* __restrict__ WT,
                     const float* __restrict__ sc7, const float* __restrict__ bi7,
                     float* __restrict__ y8, double* __restrict__ gsum, double* __restrict__ gsq){
    __shared__ float sF[16][128];
    int tid = threadIdx.x; int pn0 = blockIdx.x*16;
    for (int idx = tid; idx < 16*128; idx += 64){
        int p = idx >> 7, c = idx & 127;
        float v = y7[(size_t)(pn0+p)*128 + c];
        float h = fmaf(v, sc7[c], bi7[c]);
        sF[p][c] = (h >= 0.f) ? h : 0.2f*h;
    }
    __syncthreads();
    int o = tid;
    double s = 0.0, q = 0.0;
    for (int p0 = 0; p0 < 16; p0 += 4){
        float a0=0.f,a1=0.f,a2=0.f,a3=0.f;
        for (int c = 0; c < 128; c++){
            float w = WT[c*64 + o];
            a0 = fmaf(w, sF[p0+0][c], a0);
            a1 = fmaf(w, sF[p0+1][c], a1);
            a2 = fmaf(w, sF[p0+2][c], a2);
            a3 = fmaf(w, sF[p0+3][c], a3);
        }
        y8[(size_t)(pn0+p0+0)*64 + o] = a0;
        y8[(size_t)(pn0+p0+1)*64 + o] = a1;
        y8[(size_t)(pn0+p0+2)*64 + o] = a2;
        y8[(size_t)(pn0+p0+3)*64 + o] = a3;
        s += (double)a0 + (double)a1 + (double)a2 + (double)a3;
        q += (double)a0*a0 + (double)a1*a1 + (double)a2*a2 + (double)a3*a3;
    }
    atomicAdd(&gsum[o], s);
    atomicAdd(&gsq[o], q);
}

// ---------------- out = W9 * lrelu(bn8(y8)) ----------------
__global__ void k_out(const float* __restrict__ y8, const float* __restrict__ WT,
                      const float* __restrict__ sc8, const float* __restrict__ bi8,
                      float* __restrict__ out){
    __shared__ float sF[16][64];
    int tid = threadIdx.x; int pn0 = blockIdx.x*16;
    for (int idx = tid; idx < 16*64; idx += 128){
        int p = idx >> 6, c = idx & 63;
        float v = y8[(size_t)(pn0+p)*64 + c];
        float h = fmaf(v, sc8[c], bi8[c]);
        sF[p][c] = (h >= 0.f) ? h : 0.2f*h;
    }
    __syncthreads();
    int o = tid;
    for (int p0 = 0; p0 < 16; p0 += 4){
        float a0=0.f,a1=0.f,a2=0.f,a3=0.f;
        for (int c = 0; c < 64; c++){
            float w = WT[c*128 + o];
            a0 = fmaf(w, sF[p0+0][c], a0);
            a1 = fmaf(w, sF[p0+1][c], a1);
            a2 = fmaf(w, sF[p0+2][c], a2);
            a3 = fmaf(w, sF[p0+3][c], a3);
        }
        out[(size_t)(pn0+p0+0)*128 + o] = a0;
        out[(size_t)(pn0+p0+1)*128 + o] = a1;
        out[(size_t)(pn0+p0+2)*128 + o] = a2;
        out[(size_t)(pn0+p0+3)*128 + o] = a3;
    }
}

// ---------------- host ----------------
extern "C" void kernel_launch(void* const* d_in, const int* in_sizes, int n_in,
                              void* d_out, int out_size){
    const float* x  = (const float*)d_in[0];
    const float* xg = (const float*)d_in[1];
    const int* FPS  = (const int*)d_in[2];
    const float* W[9];
    for (int i = 0; i < 9; i++) W[i] = (const float*)d_in[3+i];
    const float *ga[8], *ba[8];
    if (in_sizes[17] == 512){           // signature order: g1..g8, b1..b8
        for (int j = 0; j < 8; j++){ ga[j] = (const float*)d_in[12+j]; ba[j] = (const float*)d_in[20+j]; }
    } else {                             // dict order: g1,b1,g2,b2,...
        for (int j = 0; j < 8; j++){ ga[j] = (const float*)d_in[12+2*j]; ba[j] = (const float*)d_in[13+2*j]; }
    }
    float* out = (float*)d_out;

    float* F; double* D;
    cudaGetSymbolAddress((void**)&F, g_f);
    cudaGetSymbolAddress((void**)&D, g_d);
    float *xp3 = F+F_XP3, *xgp3 = F+F_XGP3;
    float *x1 = F+F_X1, *x2 = F+F_X2, *x3 = F+F_X3;
    float *x1g = F+F_X1G, *x2g = F+F_X2G, *x3g = F+F_X3G;
    float *P = F+F_P, *R = F+F_R, *Q = F+F_Q, *gn = F+F_GNRM, *maxb = F+F_MAXB;
    float *y7 = F+F_Y7, *y8 = F+F_Y8;
    float *W6T = F+F_W6T, *W7BT = F+F_W7BT, *W8T = F+F_W8T, *W9T = F+F_W9T;
    float *W2T = F+F_W2T, *W4T = F+F_W4T, *c7 = F+F_C7;
    float *sc0 = F+F_SC0, *bi0 = F+F_BI0, *sc1 = F+F_SC1, *bi1 = F+F_BI1;
    double *sum0 = D, *sq0 = D+512, *sum1 = D+1024, *sq1 = D+1536;

    k_prep<<<(NB*NN*3+255)/256, 256>>>(x, xg, xp3, xgp3);
    k_wt<<<(512*192+255)/256, 256>>>(W[1], W[3], W[5], W[6], W[7], W[8],
                                     W2T, W4T, W6T, W7BT, W8T, W9T);

    dim3 gnear(NN/128, MM/64, NB);

    // ---- stage 1 (C=3, W1/W2, g1/b1, g2/b2) -> x1, x1g ----
    k_gn<3><<<(NB*MM+255)/256, 256>>>(xgp3, gn);
    k_initnear<<<(NB*NN+255)/256, 256>>>();
    k_nearest<3><<<gnear, 128>>>(xp3, xgp3, gn);
    k_nbr<3><<<NB*MM, 128>>>(xgp3, gn);
    k_pqr<3><<<NB*NN*64/128, 128>>>(xp3, W[0], P, R, NB*NN);
    k_q<3><<<NB*MM*64/128, 128>>>(xgp3, W[0], Q, NB*MM);
    k_zero<<<1, 512>>>(sum0, sq0);
    k_stats_a<<<NB*NN/16, 128>>>(P, R, Q, sum0, sq0, maxb, 0);
    k_bnparams<<<1, 512>>>(sum0, sq0, ga[0], ba[0], 64, 409600.0, sc0, bi0);
    k_zero<<<1, 512>>>(sum1, sq1);
    k_convb<<<NB*NN/4, 128>>>(P, R, Q, W2T, sc0, bi0, maxb, sum1, sq1);
    k_bnparams<<<1, 512>>>(sum1, sq1, ga[1], ba[1], 64, 409600.0, sc1, bi1);
    k_x<<<NB*NN*64/256, 256>>>(maxb, sc1, bi1, x1);
    k_gather<<<NB*MM*64/256, 256>>>(x1, FPS, x1g);

    // ---- stage 2 (C=64, W3/W4, g3/b3, g4/b4) -> x2, x2g ----
    k_gn<64><<<(NB*MM+255)/256, 256>>>(x1g, gn);
    k_initnear<<<(NB*NN+255)/256, 256>>>();
    k_nearest<64><<<gnear, 128>>>(x1, x1g, gn);
    k_nbr<64><<<NB*MM, 128>>>(x1g, gn);
    k_pqr<64><<<NB*NN*64/128, 128>>>(x1, W[2], P, R, NB*NN);
    k_q<64><<<NB*MM*64/128, 128>>>(x1g, W[2], Q, NB*MM);
    k_zero<<<1, 512>>>(sum0, sq0);
    k_stats_a<<<NB*NN/16, 128>>>(P, R, Q, sum0, sq0, maxb, 0);
    k_bnparams<<<1, 512>>>(sum0, sq0, ga[2], ba[2], 64, 409600.0, sc0, bi0);
    k_zero<<<1, 512>>>(sum1, sq1);
    k_convb<<<NB*NN/4, 128>>>(P, R, Q, W4T, sc0, bi0, maxb, sum1, sq1);
    k_bnparams<<<1, 512>>>(sum1, sq1, ga[3], ba[3], 64, 409600.0, sc1, bi1);
    k_x<<<NB*NN*64/256, 256>>>(maxb, sc1, bi1, x2);
    k_gather<<<NB*MM*64/256, 256>>>(x2, FPS, x2g);

    // ---- stage 3 (C=64, W5 only, g5/b5) -> x3, x3g ----
    k_gn<64><<<(NB*MM+255)/256, 256>>>(x2g, gn);
    k_initnear<<<(NB*NN+255)/256, 256>>>();
    k_nearest<64><<<gnear, 128>>>(x2, x2g, gn);
    k_nbr<64><<<NB*MM, 128>>>(x2g, gn);
    k_pqr<64><<<NB*NN*64/128, 128>>>(x2, W[4], P, R, NB*NN);
    k_q<64><<<NB*MM*64/128, 128>>>(x2g, W[4], Q, NB*MM);
    k_zero<<<1, 512>>>(sum0, sq0);
    k_stats_a<<<NB*NN/16, 128>>>(P, R, Q, sum0, sq0, maxb, 1);
    k_bnparams<<<1, 512>>>(sum0, sq0, ga[4], ba[4], 64, 409600.0, sc0, bi0);
    k_x<<<NB*NN*64/256, 256>>>(maxb, sc0, bi0, x3);
    k_gather<<<NB*MM*64/256, 256>>>(x3, FPS, x3g);

    // ---- tail ----
    k_zero<<<1, 512>>>(sum0, sq0);
    k_zero6<<<1, 1024>>>();
    k_y6stats<<<dim3(NB*MM/16, 4), 128>>>(x1g, x2g, x3g, W6T, sum0, sq0);
    k_bnparams<<<1, 512>>>(sum0, sq0, ga[5], ba[5], 512, 1024.0, sc0, bi0);
    k_c7<<<1, 256>>>(W[6], sc0, bi0, c7);
    k_zero<<<1, 512>>>(sum1, sq1);
    k_y7<<<NB*NN/16, 128>>>(x1, x2, x3, W7BT, c7, y7, sum1, sq1);
    k_bnparams<<<1, 512>>>(sum1, sq1, ga[6], ba[6], 128, 8192.0, sc1, bi1);
    k_zero<<<1, 512>>>(sum0, sq0);
    k_y8<<<NB*NN/16, 64>>>(y7, W8T, sc1, bi1, y8, sum0, sq0);
    k_bnparams<<<1, 512>>>(sum0, sq0, ga[7], ba[7], 64, 8192.0, sc0, bi0);
    k_out<<<NB*NN/16, 128>>>(y8, W9T, sc0, bi0, out);
}